// round 4
// baseline (speedup 1.0000x reference)
#include <cuda_runtime.h>

#define NPTS 65536
#define KC   4096
#define DIM  128
#define BN   128   // rows (n) per CTA
#define BK   128   // centroids (k) per tile
#define DC   16    // d-chunk depth staged in smem

// Single fused kernel: distance-argmin over all centroids.
// score(n,k) = ||c_k||^2 - 2 * dot(x_n, c_k)   (x^2 row-constant, sqrt monotone)
// Output written as FLOAT (harness __output__ dtype is float — int writes
// read back as denormals and produced the observed rel_err == 1.0 exactly).
__global__ __launch_bounds__(256) void nn_fused_kernel(
    const float* __restrict__ latent,   // [NPTS][DIM] row-major f32
    const float* __restrict__ coords,   // [KC][DIM]   row-major f32
    float* __restrict__ out)            // [NPTS] float32 (index values)
{
    __shared__ float As[DC * BN];    // [d][n] transposed tile
    __shared__ float Bs[DC * BK];    // [d][k] transposed tile
    __shared__ float c2s[BK];        // ||c_k||^2 for current k-tile
    __shared__ float rv[BN * 16];    // reduction values
    __shared__ int   ri[BN * 16];    // reduction indices

    const int tid = threadIdx.x;
    const int tx  = tid & 15;        // k group
    const int ty  = tid >> 4;        // n group
    const int n0  = blockIdx.x * BN;

    float runval[8];
    int   runidx[8];
    #pragma unroll
    for (int i = 0; i < 8; ++i) { runval[i] = 3.0e38f; runidx[i] = 0; }

    const float4* lat4 = (const float4*)latent;
    const float4* coo4 = (const float4*)coords;

    for (int kt = 0; kt < KC / BK; ++kt) {
        const int k0 = kt * BK;

        __syncthreads();   // protect Bs/c2s from previous-iteration readers

        // --- c2 pre-phase: threads 0..127 each compute ||coords[k0+t]||^2 ---
        if (tid < BK) {
            const float4* row = coo4 + (size_t)(k0 + tid) * (DIM / 4);
            float s0 = 0.f, s1 = 0.f, s2 = 0.f, s3 = 0.f;
            #pragma unroll 8
            for (int q = 0; q < DIM / 4; ++q) {
                float4 v = row[q];
                s0 = fmaf(v.x, v.x, s0);
                s1 = fmaf(v.y, v.y, s1);
                s2 = fmaf(v.z, v.z, s2);
                s3 = fmaf(v.w, v.w, s3);
            }
            c2s[tid] = (s0 + s1) + (s2 + s3);
        }

        float acc[8][8];
        #pragma unroll
        for (int i = 0; i < 8; ++i)
            #pragma unroll
            for (int j = 0; j < 8; ++j) acc[i][j] = 0.0f;

        for (int dc0 = 0; dc0 < DIM; dc0 += DC) {
            __syncthreads();
            // --- stage A chunk: As[d][n] <- latent[n0+n][dc0+d] (transpose) ---
            #pragma unroll
            for (int it = 0; it < 2; ++it) {
                int idx = tid + it * 256;          // 0..511
                int n = idx >> 2;                  // 0..127
                int q = idx & 3;                   // float4 within 16-float chunk
                float4 v = lat4[(size_t)(n0 + n) * (DIM / 4) + (dc0 >> 2) + q];
                As[(q * 4 + 0) * BN + n] = v.x;
                As[(q * 4 + 1) * BN + n] = v.y;
                As[(q * 4 + 2) * BN + n] = v.z;
                As[(q * 4 + 3) * BN + n] = v.w;
            }
            // --- stage B chunk: Bs[d][k] <- coords[k0+k][dc0+d] (transpose) ---
            #pragma unroll
            for (int it = 0; it < 2; ++it) {
                int idx = tid + it * 256;
                int k = idx >> 2;
                int q = idx & 3;
                float4 v = coo4[(size_t)(k0 + k) * (DIM / 4) + (dc0 >> 2) + q];
                Bs[(q * 4 + 0) * BK + k] = v.x;
                Bs[(q * 4 + 1) * BK + k] = v.y;
                Bs[(q * 4 + 2) * BK + k] = v.z;
                Bs[(q * 4 + 3) * BK + k] = v.w;
            }
            __syncthreads();

            // --- FMA core: 8x8 register tile over DC depth ---
            #pragma unroll
            for (int d = 0; d < DC; ++d) {
                float4 a0 = *(const float4*)&As[d * BN + ty * 8];
                float4 a1 = *(const float4*)&As[d * BN + ty * 8 + 4];
                float4 b0 = *(const float4*)&Bs[d * BK + tx * 8];
                float4 b1 = *(const float4*)&Bs[d * BK + tx * 8 + 4];
                float a[8] = {a0.x, a0.y, a0.z, a0.w, a1.x, a1.y, a1.z, a1.w};
                float b[8] = {b0.x, b0.y, b0.z, b0.w, b1.x, b1.y, b1.z, b1.w};
                #pragma unroll
                for (int i = 0; i < 8; ++i)
                    #pragma unroll
                    for (int j = 0; j < 8; ++j)
                        acc[i][j] = fmaf(a[i], b[j], acc[i][j]);
            }
        }

        // --- argmin epilogue for this k-tile (strict '<' keeps first
        //     occurrence; per-thread k ascends, matching jnp.argmin ties) ---
        #pragma unroll
        for (int j = 0; j < 8; ++j) {
            int k = k0 + tx * 8 + j;
            float c2 = c2s[tx * 8 + j];
            #pragma unroll
            for (int i = 0; i < 8; ++i) {
                float s = fmaf(-2.0f, acc[i][j], c2);
                if (s < runval[i]) { runval[i] = s; runidx[i] = k; }
            }
        }
    }

    // --- cross-thread reduction: 16 candidates per row ---
    __syncthreads();
    #pragma unroll
    for (int i = 0; i < 8; ++i) {
        int row = ty * 8 + i;
        rv[row * 16 + tx] = runval[i];
        ri[row * 16 + tx] = runidx[i];
    }
    __syncthreads();
    if (tid < BN) {
        float bv = rv[tid * 16];
        int   bi = ri[tid * 16];
        #pragma unroll
        for (int c = 1; c < 16; ++c) {
            float v  = rv[tid * 16 + c];
            int   id = ri[tid * 16 + c];
            if (v < bv || (v == bv && id < bi)) { bv = v; bi = id; }
        }
        out[n0 + tid] = (float)bi;   // FLOAT output
    }
}

extern "C" void kernel_launch(void* const* d_in, const int* in_sizes, int n_in,
                              void* d_out, int out_size) {
    // Identify inputs by element count (robust to metadata ordering):
    // latent = 65536*128 = 8388608, coords = 4096*128 = 524288.
    const float* latent;
    const float* coords;
    if (in_sizes[0] == NPTS * DIM) {
        latent = (const float*)d_in[0];
        coords = (const float*)d_in[1];
    } else {
        latent = (const float*)d_in[1];
        coords = (const float*)d_in[0];
    }
    float* out = (float*)d_out;

    nn_fused_kernel<<<NPTS / BN, 256>>>(latent, coords, out);
}

// round 5
// speedup vs baseline: 1.5180x; 1.5180x over previous
#include <cuda_runtime.h>

#define NPTS 65536
#define KC   4096
#define DIM  128
#define BN   128            // n rows per CTA
#define BK   256            // k centroids per tile
#define NKT  (KC / BK)      // 16 k-tiles

// Device scratch (allocation-free rule)
__device__ float g_latT[DIM * NPTS];   // latent transposed [D][N], 32 MB
__device__ float g_cooT[DIM * KC];     // coords transposed [D][K], 2 MB
__device__ float g_c2[KC];             // ||c_k||^2

// ---------------- packed f32x2 helpers (FFMA2 — PTX-only pattern) ----------
__device__ __forceinline__ unsigned long long pack2(float v) {
    unsigned long long r;
    unsigned int u = __float_as_uint(v);
    asm("mov.b64 %0, {%1, %2};" : "=l"(r) : "r"(u), "r"(u));
    return r;
}
__device__ __forceinline__ void fma2(unsigned long long& d,
                                     unsigned long long a,
                                     unsigned long long b) {
    asm("fma.rn.f32x2 %0, %1, %2, %0;" : "+l"(d) : "l"(a), "l"(b));
}
__device__ __forceinline__ float2 unpack2(unsigned long long v) {
    unsigned int lo, hi;
    asm("mov.b64 {%0, %1}, %2;" : "=r"(lo), "=r"(hi) : "l"(v));
    return make_float2(__uint_as_float(lo), __uint_as_float(hi));
}

// ---------------- Prologue 1: latent [N][D] -> g_latT [D][N] ---------------
__global__ void transpose_lat_kernel(const float* __restrict__ in) {
    __shared__ float tile[32][33];
    const int c0 = blockIdx.x * 32;   // d base
    const int r0 = blockIdx.y * 32;   // n base
    const int x = threadIdx.x, y = threadIdx.y;  // 32 x 8
    #pragma unroll
    for (int i = 0; i < 32; i += 8)
        tile[y + i][x] = in[(size_t)(r0 + y + i) * DIM + c0 + x];
    __syncthreads();
    #pragma unroll
    for (int i = 0; i < 32; i += 8)
        g_latT[(size_t)(c0 + y + i) * NPTS + r0 + x] = tile[x][y + i];
}

// ---------------- Prologue 2: coords [K][D] -> g_cooT [D][K] ---------------
__global__ void transpose_coo_kernel(const float* __restrict__ in) {
    __shared__ float tile[32][33];
    const int c0 = blockIdx.x * 32;   // d base
    const int r0 = blockIdx.y * 32;   // k base
    const int x = threadIdx.x, y = threadIdx.y;
    #pragma unroll
    for (int i = 0; i < 32; i += 8)
        tile[y + i][x] = in[(size_t)(r0 + y + i) * DIM + c0 + x];
    __syncthreads();
    #pragma unroll
    for (int i = 0; i < 32; i += 8)
        g_cooT[(size_t)(c0 + y + i) * KC + r0 + x] = tile[x][y + i];
}

// ---------------- Prologue 3: c2[k] = sum_d cooT[d][k]^2 -------------------
__global__ void c2_kernel() {
    int k = blockIdx.x * blockDim.x + threadIdx.x;
    if (k >= KC) return;
    float s = 0.0f;
    #pragma unroll 8
    for (int d = 0; d < DIM; ++d) {
        float v = g_cooT[d * KC + k];
        s = fmaf(v, v, s);
    }
    g_c2[k] = s;
}

// ---------------- Main: fused FFMA2 GEMM + argmin --------------------------
// smem: As[128][128] (64KB, persistent) + Bs[128][256] (128KB) + c2s[256]
// Thread (tx=tid&15, ty=tid>>4): 8 n-rows x 16 k-cols register tile.
//   n_i = ty*4 + (i&3) + 64*(i>>2),  k = g*64 + tx*4 + j  (g<4, j<4)
__global__ __launch_bounds__(256, 1) void nn_kernel(float* __restrict__ out) {
    extern __shared__ float sm[];
    float* As  = sm;                       // 128*128 floats
    float* Bs  = sm + BN * DIM;            // 128*256 floats (d-major)
    float* c2s = sm + BN * DIM + DIM * BK; // 256 floats

    const int tid = threadIdx.x;
    const int tx  = tid & 15;
    const int ty  = tid >> 4;
    const int n0  = blockIdx.x * BN;

    // ---- stage A once: As[d][n] <- g_latT[d][n0+n], coalesced float4 ----
    {
        const float4* src = (const float4*)g_latT;
        float4* dst = (float4*)As;
        #pragma unroll
        for (int it = 0; it < 16; ++it) {
            int idx = tid + it * 256;          // 0..4095
            int d  = idx >> 5;
            int nq = idx & 31;
            dst[d * 32 + nq] = src[(size_t)d * (NPTS / 4) + (n0 >> 2) + nq];
        }
    }

    float runval[8];
    int   runidx[8];
    #pragma unroll
    for (int i = 0; i < 8; ++i) { runval[i] = 3.0e38f; runidx[i] = 0; }

    for (int kt = 0; kt < NKT; ++kt) {
        const int k0 = kt * BK;
        __syncthreads();   // protect Bs/c2s from previous iteration readers

        // ---- stage B tile: Bs[d][k] <- g_cooT[d][k0+k], coalesced ----
        {
            const float4* src = (const float4*)g_cooT;
            float4* dst = (float4*)Bs;
            #pragma unroll
            for (int it = 0; it < 32; ++it) {
                int idx = tid + it * 256;      // 0..8191
                int d  = idx >> 6;
                int kq = idx & 63;
                dst[d * 64 + kq] = src[(size_t)d * (KC / 4) + (k0 >> 2) + kq];
            }
        }
        if (tid < 64) {
            ((float4*)c2s)[tid] = ((const float4*)g_c2)[(k0 >> 2) + tid];
        }
        __syncthreads();

        // ---- FFMA2 core: 8n x 16k register tile, acc as f32x2 pairs ----
        unsigned long long acc[8][8];   // [i][g*2+h], h = k-pair within quad
        #pragma unroll
        for (int i = 0; i < 8; ++i)
            #pragma unroll
            for (int p = 0; p < 8; ++p) acc[i][p] = 0ull;

        #pragma unroll 4
        for (int d = 0; d < DIM; ++d) {
            const float* Ad = &As[d * BN + ty * 4];
            float4 a0 = *(const float4*)Ad;
            float4 a1 = *(const float4*)(Ad + 64);
            unsigned long long ad[8] = {
                pack2(a0.x), pack2(a0.y), pack2(a0.z), pack2(a0.w),
                pack2(a1.x), pack2(a1.y), pack2(a1.z), pack2(a1.w)};
            const float* Bd = &Bs[d * BK + tx * 4];
            ulonglong2 b0 = *(const ulonglong2*)(Bd);
            ulonglong2 b1 = *(const ulonglong2*)(Bd + 64);
            ulonglong2 b2 = *(const ulonglong2*)(Bd + 128);
            ulonglong2 b3 = *(const ulonglong2*)(Bd + 192);
            #pragma unroll
            for (int i = 0; i < 8; ++i) {
                fma2(acc[i][0], ad[i], b0.x);
                fma2(acc[i][1], ad[i], b0.y);
                fma2(acc[i][2], ad[i], b1.x);
                fma2(acc[i][3], ad[i], b1.y);
                fma2(acc[i][4], ad[i], b2.x);
                fma2(acc[i][5], ad[i], b2.y);
                fma2(acc[i][6], ad[i], b3.x);
                fma2(acc[i][7], ad[i], b3.y);
            }
        }

        // ---- argmin epilogue: per-thread k ascends (g,h,lo/hi; kt outer);
        //      strict '<' keeps first occurrence (jnp.argmin tie rule) ----
        #pragma unroll
        for (int g = 0; g < 4; ++g) {
            #pragma unroll
            for (int h = 0; h < 2; ++h) {
                int kc = g * 64 + tx * 4 + h * 2;
                float c2a = c2s[kc];
                float c2b = c2s[kc + 1];
                #pragma unroll
                for (int i = 0; i < 8; ++i) {
                    float2 v = unpack2(acc[i][g * 2 + h]);
                    float s0 = fmaf(-2.0f, v.x, c2a);
                    float s1 = fmaf(-2.0f, v.y, c2b);
                    if (s0 < runval[i]) { runval[i] = s0; runidx[i] = k0 + kc; }
                    if (s1 < runval[i]) { runval[i] = s1; runidx[i] = k0 + kc + 1; }
                }
            }
        }
    }

    // ---- cross-thread reduction (overlay As region) ----
    __syncthreads();
    float* rv = sm;                       // [128][16]
    int*   ri = (int*)(sm + BN * 16);     // [128][16]
    #pragma unroll
    for (int i = 0; i < 8; ++i) {
        int n = ty * 4 + (i & 3) + 64 * (i >> 2);
        rv[n * 16 + tx] = runval[i];
        ri[n * 16 + tx] = runidx[i];
    }
    __syncthreads();
    if (tid < BN) {
        float bv = rv[tid * 16];
        int   bi = ri[tid * 16];
        #pragma unroll
        for (int c = 1; c < 16; ++c) {
            float v  = rv[tid * 16 + c];
            int   id = ri[tid * 16 + c];
            if (v < bv || (v == bv && id < bi)) { bv = v; bi = id; }
        }
        out[n0 + tid] = (float)bi;   // float output (verified contract)
    }
}

// ---------------------------------------------------------------------------
extern "C" void kernel_launch(void* const* d_in, const int* in_sizes, int n_in,
                              void* d_out, int out_size) {
    // Identify inputs by element count (robust to metadata ordering).
    const float* latent;
    const float* coords;
    if (in_sizes[0] == NPTS * DIM) {
        latent = (const float*)d_in[0];
        coords = (const float*)d_in[1];
    } else {
        latent = (const float*)d_in[1];
        coords = (const float*)d_in[0];
    }
    float* out = (float*)d_out;

    const int smem_bytes = (BN * DIM + DIM * BK + BK) * sizeof(float); // 197632
    cudaFuncSetAttribute(nn_kernel, cudaFuncAttributeMaxDynamicSharedMemorySize,
                         smem_bytes);

    dim3 tb(32, 8);
    transpose_lat_kernel<<<dim3(DIM / 32, NPTS / 32), tb>>>(latent);
    transpose_coo_kernel<<<dim3(DIM / 32, KC / 32), tb>>>(coords);
    c2_kernel<<<KC / 256, 256>>>();
    nn_kernel<<<NPTS / BN, 256, smem_bytes>>>(out);
}

// round 7
// speedup vs baseline: 2.1311x; 1.4039x over previous
#include <cuda_runtime.h>
#include <cuda_bf16.h>
#include <cstdint>

#define NPTS 65536
#define KC   4096
#define DIM  128
#define BN   128          // n rows per CTA
#define BK   128          // centroids per k-tile
#define KHALF 2048        // k range per CTA (2 halves)

// Device scratch (allocation-free rule)
__device__ __nv_bfloat16 g_a0[NPTS * DIM];
__device__ __nv_bfloat16 g_a1[NPTS * DIM];
__device__ __nv_bfloat16 g_a2[NPTS * DIM];
__device__ __nv_bfloat16 g_b0[KC * DIM];
__device__ __nv_bfloat16 g_b1[KC * DIM];
__device__ __nv_bfloat16 g_b2[KC * DIM];
__device__ float         g_c2[KC];
__device__ unsigned long long g_best[NPTS];   // (score_key << 32) | idx

// ---------------------------------------------------------------------------
__device__ __forceinline__ uint32_t smem_u32(const void* p) {
    uint32_t a;
    asm("{ .reg .u64 t; cvta.to.shared.u64 t, %1; cvt.u32.u64 %0, t; }"
        : "=r"(a) : "l"(p));
    return a;
}
// Monotonic uint encoding of float (order-preserving)
__device__ __forceinline__ uint32_t fkey(float f) {
    uint32_t u = __float_as_uint(f);
    return (u & 0x80000000u) ? ~u : (u | 0x80000000u);
}
#define LDSM_X4(r0, r1, r2, r3, addr) \
    asm volatile("ldmatrix.sync.aligned.m8n8.x4.shared.b16 {%0,%1,%2,%3}, [%4];" \
                 : "=r"(r0), "=r"(r1), "=r"(r2), "=r"(r3) : "r"(addr))
#define MMA_BF16(c, a, b0v, b1v) \
    asm volatile("mma.sync.aligned.m16n8k16.row.col.f32.bf16.bf16.f32 " \
                 "{%0,%1,%2,%3}, {%4,%5,%6,%7}, {%8,%9}, {%0,%1,%2,%3};" \
                 : "+f"((c)[0]), "+f"((c)[1]), "+f"((c)[2]), "+f"((c)[3]) \
                 : "r"((a)[0]), "r"((a)[1]), "r"((a)[2]), "r"((a)[3]), \
                   "r"(b0v), "r"(b1v))

// ---------------------------------------------------------------------------
// Prologues: 3-way bf16 split of latent/coords + exact fp32 c2, g_best init
// ---------------------------------------------------------------------------
__global__ void split_lat_kernel(const float* __restrict__ in) {
    int i = blockIdx.x * blockDim.x + threadIdx.x;
    if (i >= NPTS * DIM) return;
    float v = in[i];
    __nv_bfloat16 b0 = __float2bfloat16(v);
    float r1 = v - __bfloat162float(b0);
    __nv_bfloat16 b1 = __float2bfloat16(r1);
    float r2 = r1 - __bfloat162float(b1);
    g_a0[i] = b0; g_a1[i] = b1; g_a2[i] = __float2bfloat16(r2);
}
__global__ void split_coo_kernel(const float* __restrict__ in) {
    int i = blockIdx.x * blockDim.x + threadIdx.x;
    if (i >= KC * DIM) return;
    float v = in[i];
    __nv_bfloat16 b0 = __float2bfloat16(v);
    float r1 = v - __bfloat162float(b0);
    __nv_bfloat16 b1 = __float2bfloat16(r1);
    float r2 = r1 - __bfloat162float(b1);
    g_b0[i] = b0; g_b1[i] = b1; g_b2[i] = __float2bfloat16(r2);
}
__global__ void c2_kernel(const float* __restrict__ coords) {
    int k = blockIdx.x * blockDim.x + threadIdx.x;
    if (k >= KC) return;
    const float* row = coords + (size_t)k * DIM;
    float s = 0.f;
    #pragma unroll 8
    for (int d = 0; d < DIM; ++d) s = fmaf(row[d], row[d], s);
    g_c2[k] = s;
}
__global__ void init_best_kernel() {
    int i = blockIdx.x * blockDim.x + threadIdx.x;
    if (i < NPTS) g_best[i] = 0xFFFFFFFFFFFFFFFFull;
}
__global__ void final_kernel(float* __restrict__ out) {
    int i = blockIdx.x * blockDim.x + threadIdx.x;
    if (i < NPTS) out[i] = (float)(uint32_t)(g_best[i] & 0xFFFFFFFFull);
}

// ---------------------------------------------------------------------------
// Main: HMMA bf16 3-way-split GEMM + fused argmin, atomicMin merge.
// 256 threads = warp grid 4(M) x 2(N). Warp tile 32(M) x 64(N) per k-tile.
// smem: A planes 0/32K/64K, B planes 96K/128K/160K, c2s @192K. Swizzle:
// plane row = 256B = 16 granules of 16B; phys granule = g ^ (row & 7).
// ---------------------------------------------------------------------------
__global__ __launch_bounds__(256, 1) void nn_hmma_kernel() {
    extern __shared__ char smem[];
    const uint32_t sbase = smem_u32(smem);
    float* c2s = (float*)(smem + 196608);

    const int tid = threadIdx.x;
    const int L   = tid & 31;
    const int wid = tid >> 5;
    const int wm  = wid >> 1;       // 0..3 (M)
    const int wn  = wid & 1;        // 0..1 (N)
    const int n0  = (blockIdx.x >> 1) * BN;
    const int kb  = (blockIdx.x & 1) * KHALF;

    // ---- stage A splits (once): 3 planes, swizzled ----
    {
        const __nv_bfloat16* gA[3] = {g_a0, g_a1, g_a2};
        #pragma unroll
        for (int s = 0; s < 3; ++s) {
            #pragma unroll
            for (int it = 0; it < 8; ++it) {
                int Gi = tid + it * 256;            // 0..2047
                int row = Gi >> 4, g = Gi & 15;
                uint4 v = *((const uint4*)(gA[s] + (size_t)(n0 + row) * DIM) + g);
                *(uint4*)(smem + s * 32768 + row * 256 + ((g ^ (row & 7)) << 4)) = v;
            }
        }
    }

    // ldmatrix lane-address constants
    const int aBase = 32 * wm + ((L >> 3) & 1) * 8 + (L & 7);
    const int aG    = (L >> 4);
    const int sxa   = aBase & 7;
    const int bBase = 64 * wn + ((L >> 4)) * 8 + (L & 7);
    const int bG    = (L >> 3) & 1;
    const int sxb   = bBase & 7;
    const uint32_t aAddr0 = sbase + aBase * 256;
    const uint32_t bAddr0 = sbase + 98304 + bBase * 256;

    float rval[4];
    int   ridx[4];
    #pragma unroll
    for (int i = 0; i < 4; ++i) { rval[i] = 3.0e38f; ridx[i] = 0; }

    const __nv_bfloat16* gB[3] = {g_b0, g_b1, g_b2};
    const int PA[6] = {0, 1, 2, 0, 1, 0};
    const int PB[6] = {0, 0, 0, 1, 1, 2};

    for (int kt = 0; kt < KHALF / BK; ++kt) {
        const int k0 = kb + kt * BK;
        __syncthreads();
        // ---- stage B splits for this k-tile ----
        #pragma unroll
        for (int s = 0; s < 3; ++s) {
            #pragma unroll
            for (int it = 0; it < 8; ++it) {
                int Gi = tid + it * 256;
                int row = Gi >> 4, g = Gi & 15;
                uint4 v = *((const uint4*)(gB[s] + (size_t)(k0 + row) * DIM) + g);
                *(uint4*)(smem + 98304 + s * 32768 + row * 256 +
                          ((g ^ (row & 7)) << 4)) = v;
            }
        }
        if (tid < BK) c2s[tid] = g_c2[k0 + tid];
        __syncthreads();

        float acc[2][8][4];
        #pragma unroll
        for (int bi = 0; bi < 2; ++bi)
            #pragma unroll
            for (int nb = 0; nb < 8; ++nb)
                #pragma unroll
                for (int c = 0; c < 4; ++c) acc[bi][nb][c] = 0.0f;

        for (int p = 0; p < 6; ++p) {
            const uint32_t SAp = aAddr0 + PA[p] * 32768;
            const uint32_t SBp = bAddr0 + PB[p] * 32768;
            #pragma unroll
            for (int kk = 0; kk < 8; ++kk) {
                uint32_t a[2][4];
                #pragma unroll
                for (int bi = 0; bi < 2; ++bi) {
                    uint32_t ad = SAp + bi * 4096 + (((2 * kk + aG) ^ sxa) << 4);
                    LDSM_X4(a[bi][0], a[bi][1], a[bi][2], a[bi][3], ad);
                }
                uint32_t b[4][4];
                #pragma unroll
                for (int i = 0; i < 4; ++i) {
                    uint32_t bd = SBp + i * 4096 + (((2 * kk + bG) ^ sxb) << 4);
                    LDSM_X4(b[i][0], b[i][1], b[i][2], b[i][3], bd);
                }
                #pragma unroll
                for (int bi = 0; bi < 2; ++bi)
                    #pragma unroll
                    for (int nb = 0; nb < 8; ++nb) {
                        const uint32_t* bp = b[nb >> 1];
                        if (nb & 1) MMA_BF16(acc[bi][nb], a[bi], bp[2], bp[3]);
                        else        MMA_BF16(acc[bi][nb], a[bi], bp[0], bp[1]);
                    }
            }
        }

        // ---- fused argmin epilogue (k ascends per slot; strict '<' = first
        //      occurrence, jnp.argmin tie rule) ----
        #pragma unroll
        for (int bi = 0; bi < 2; ++bi)
            #pragma unroll
            for (int nb = 0; nb < 8; ++nb) {
                int ncol = 64 * wn + 8 * nb + 2 * (L & 3);
                float c2a = c2s[ncol], c2b = c2s[ncol + 1];
                int kidx = k0 + ncol;
                #pragma unroll
                for (int h = 0; h < 2; ++h) {
                    int r = bi * 2 + h;
                    float s0 = fmaf(-2.0f, acc[bi][nb][h * 2 + 0], c2a);
                    float s1 = fmaf(-2.0f, acc[bi][nb][h * 2 + 1], c2b);
                    if (s0 < rval[r]) { rval[r] = s0; ridx[r] = kidx; }
                    if (s1 < rval[r]) { rval[r] = s1; ridx[r] = kidx + 1; }
                }
            }
    }

    // ---- intra-CTA merge (8 slots per row), then global atomicMin ----
    __syncthreads();
    float* rv = (float*)(smem + 98304);
    int*   ri = (int*)(smem + 98304 + 128 * 8 * 4);
    #pragma unroll
    for (int bi = 0; bi < 2; ++bi)
        #pragma unroll
        for (int h = 0; h < 2; ++h) {
            int row  = 32 * wm + 16 * bi + 8 * h + (L >> 2);
            int slot = wn * 4 + (L & 3);
            rv[row * 8 + slot] = rval[bi * 2 + h];
            ri[row * 8 + slot] = ridx[bi * 2 + h];
        }
    __syncthreads();
    if (tid < BN) {
        float bv = rv[tid * 8];
        int   bi = ri[tid * 8];
        #pragma unroll
        for (int c = 1; c < 8; ++c) {
            float v  = rv[tid * 8 + c];
            int   id = ri[tid * 8 + c];
            if (v < bv || (v == bv && id < bi)) { bv = v; bi = id; }
        }
        unsigned long long key =
            ((unsigned long long)fkey(bv) << 32) | (unsigned int)bi;
        atomicMin(&g_best[n0 + tid], key);
    }
}

// ---------------------------------------------------------------------------
extern "C" void kernel_launch(void* const* d_in, const int* in_sizes, int n_in,
                              void* d_out, int out_size) {
    const float* latent;
    const float* coords;
    if (in_sizes[0] == NPTS * DIM) {
        latent = (const float*)d_in[0];
        coords = (const float*)d_in[1];
    } else {
        latent = (const float*)d_in[1];
        coords = (const float*)d_in[0];
    }
    float* out = (float*)d_out;

    const int smem_bytes = 196608 + 512 + 128;   // A+B planes, c2s
    cudaFuncSetAttribute(nn_hmma_kernel,
                         cudaFuncAttributeMaxDynamicSharedMemorySize, smem_bytes);

    init_best_kernel<<<NPTS / 256, 256>>>();
    split_lat_kernel<<<(NPTS * DIM) / 256, 256>>>(latent);
    split_coo_kernel<<<(KC * DIM) / 256, 256>>>(coords);
    c2_kernel<<<KC / 256, 256>>>(coords);
    nn_hmma_kernel<<<(NPTS / BN) * 2, 256, smem_bytes>>>();
    final_kernel<<<NPTS / 256, 256>>>(out);
}

// round 8
// speedup vs baseline: 3.5343x; 1.6584x over previous
#include <cuda_runtime.h>
#include <cuda_bf16.h>
#include <cstdint>

#define NPTS 65536
#define KC   4096
#define DIM  128
#define BN   128          // n rows per CTA
#define BK   128          // centroids per k-tile
#define KHALF 2048        // k range per CTA
#define NT   (KHALF / BK) // 16 tiles

// Device scratch (allocation-free rule)
__device__ __nv_bfloat16 g_a0[NPTS * DIM];
__device__ __nv_bfloat16 g_a1[NPTS * DIM];
__device__ __nv_bfloat16 g_b0[KC * DIM];
__device__ __nv_bfloat16 g_b1[KC * DIM];
__device__ float         g_c2[KC];
__device__ unsigned long long g_best[NPTS];   // (fkey(score) << 32) | idx

// ---------------------------------------------------------------------------
__device__ __forceinline__ uint32_t smem_u32(const void* p) {
    uint32_t a;
    asm("{ .reg .u64 t; cvta.to.shared.u64 t, %1; cvt.u32.u64 %0, t; }"
        : "=r"(a) : "l"(p));
    return a;
}
__device__ __forceinline__ uint32_t fkey(float f) {      // order-preserving
    uint32_t u = __float_as_uint(f);
    return (u & 0x80000000u) ? ~u : (u | 0x80000000u);
}
#define LDSM_X4(r0, r1, r2, r3, addr) \
    asm volatile("ldmatrix.sync.aligned.m8n8.x4.shared.b16 {%0,%1,%2,%3}, [%4];" \
                 : "=r"(r0), "=r"(r1), "=r"(r2), "=r"(r3) : "r"(addr))
#define MMA_BF16(c, a, b0v, b1v) \
    asm volatile("mma.sync.aligned.m16n8k16.row.col.f32.bf16.bf16.f32 " \
                 "{%0,%1,%2,%3}, {%4,%5,%6,%7}, {%8,%9}, {%0,%1,%2,%3};" \
                 : "+f"((c)[0]), "+f"((c)[1]), "+f"((c)[2]), "+f"((c)[3]) \
                 : "r"((a)[0]), "r"((a)[1]), "r"((a)[2]), "r"((a)[3]), \
                   "r"(b0v), "r"(b1v))
__device__ __forceinline__ void cp16(uint32_t dst, const void* src) {
    asm volatile("cp.async.cg.shared.global [%0], [%1], 16;"
                 :: "r"(dst), "l"(src));
}
#define CP_COMMIT() asm volatile("cp.async.commit_group;" ::: "memory")
#define CP_WAIT0()  asm volatile("cp.async.wait_group 0;" ::: "memory")

// ---------------------------------------------------------------------------
// Prologues
// ---------------------------------------------------------------------------
__global__ void split_lat_kernel(const float* __restrict__ in) {
    int i = blockIdx.x * blockDim.x + threadIdx.x;
    if (i >= NPTS * DIM) return;
    float v = in[i];
    __nv_bfloat16 b0 = __float2bfloat16(v);
    float r1 = v - __bfloat162float(b0);
    g_a0[i] = b0; g_a1[i] = __float2bfloat16(r1);
}
__global__ void split_coo_kernel(const float* __restrict__ in) {
    int i = blockIdx.x * blockDim.x + threadIdx.x;
    if (i >= KC * DIM) return;
    float v = in[i];
    __nv_bfloat16 b0 = __float2bfloat16(v);
    float r1 = v - __bfloat162float(b0);
    g_b0[i] = b0; g_b1[i] = __float2bfloat16(r1);
}
__global__ void c2_kernel(const float* __restrict__ coords) {
    // one warp per row, float4 per lane
    int row  = blockIdx.x * 8 + (threadIdx.x >> 5);
    int lane = threadIdx.x & 31;
    float4 v = ((const float4*)(coords + (size_t)row * DIM))[lane];
    float s = fmaf(v.x, v.x, fmaf(v.y, v.y, fmaf(v.z, v.z, v.w * v.w)));
    #pragma unroll
    for (int o = 16; o; o >>= 1) s += __shfl_xor_sync(0xFFFFFFFFu, s, o);
    if (lane == 0) g_c2[row] = s;
}
__global__ void init_best_kernel() {
    int i = blockIdx.x * blockDim.x + threadIdx.x;
    if (i < NPTS) g_best[i] = 0xFFFFFFFFFFFFFFFFull;
}
__global__ void final_kernel(float* __restrict__ out) {
    int i = blockIdx.x * blockDim.x + threadIdx.x;
    if (i < NPTS) out[i] = (float)(uint32_t)(g_best[i] & 0xFFFFFFFFull);
}

// ---------------------------------------------------------------------------
// Main: HMMA bf16 2x2-split GEMM + fused argmin, cp.async double-buffered B.
// 256 threads = warp grid 4(M) x 2(N); warp tile 32(M) x 64(N).
// smem: A0 @0, A1 @32K; B[st][pl] @ 64K + st*64K + pl*32K  (192 KB total).
// Plane layout: 256B rows (128 bf16), 16B granule swizzle g ^= (row & 7).
// ---------------------------------------------------------------------------
__global__ __launch_bounds__(256, 1) void nn_hmma_kernel() {
    extern __shared__ char smem[];
    const uint32_t sbase = smem_u32(smem);

    const int tid = threadIdx.x;
    const int L   = tid & 31;
    const int wid = tid >> 5;
    const int wm  = wid >> 1;       // 0..3 (M)
    const int wn  = wid & 1;        // 0..1 (N)
    const int n0  = (blockIdx.x >> 1) * BN;
    const int kb  = (blockIdx.x & 1) * KHALF;

    // ---- stage A splits once (plain stores) ----
    {
        const __nv_bfloat16* gA[2] = {g_a0, g_a1};
        #pragma unroll
        for (int s = 0; s < 2; ++s)
            #pragma unroll
            for (int it = 0; it < 8; ++it) {
                int Gi = tid + it * 256;
                int row = Gi >> 4, g = Gi & 15;
                uint4 v = *((const uint4*)(gA[s] + (size_t)(n0 + row) * DIM) + g);
                *(uint4*)(smem + s * 32768 + row * 256 + ((g ^ (row & 7)) << 4)) = v;
            }
    }

    // ---- B staging via cp.async ----
    auto stage_b = [&](int st, int k0) {
        #pragma unroll
        for (int s = 0; s < 2; ++s) {
            const __nv_bfloat16* gb = s ? g_b1 : g_b0;
            #pragma unroll
            for (int it = 0; it < 8; ++it) {
                int Gi = tid + it * 256;
                int row = Gi >> 4, g = Gi & 15;
                uint32_t dst = sbase + 65536 + st * 65536 + s * 32768 +
                               row * 256 + ((g ^ (row & 7)) << 4);
                cp16(dst, gb + (size_t)(k0 + row) * DIM + g * 8);
            }
        }
    };
    stage_b(0, kb);
    CP_COMMIT();

    // ldmatrix lane-address constants (verified in R7)
    const int aBase = 32 * wm + ((L >> 3) & 1) * 8 + (L & 7);
    const int aG    = (L >> 4);
    const int sxa   = aBase & 7;
    const int bBase = 64 * wn + (L >> 4) * 8 + (L & 7);
    const int bG    = (L >> 3) & 1;
    const int sxb   = bBase & 7;
    const uint32_t aAddr0 = sbase + aBase * 256;

    float rval[4];
    int   ridx[4];
    #pragma unroll
    for (int i = 0; i < 4; ++i) { rval[i] = 3.0e38f; ridx[i] = 0; }

    for (int kt = 0; kt < NT; ++kt) {
        const int st = kt & 1;
        const int k0 = kb + kt * BK;

        CP_WAIT0();
        __syncthreads();
        if (kt + 1 < NT) { stage_b(st ^ 1, k0 + BK); CP_COMMIT(); }

        const uint32_t bAddr = sbase + 65536 + st * 65536 + bBase * 256;

        float acc[2][8][4];
        #pragma unroll
        for (int bi = 0; bi < 2; ++bi)
            #pragma unroll
            for (int nb = 0; nb < 8; ++nb)
                #pragma unroll
                for (int c = 0; c < 4; ++c) acc[bi][nb][c] = 0.0f;

        #pragma unroll
        for (int kk = 0; kk < 8; ++kk) {
            uint32_t a[2][2][4];                 // [plane][bi]
            #pragma unroll
            for (int pl = 0; pl < 2; ++pl)
                #pragma unroll
                for (int bi = 0; bi < 2; ++bi) {
                    uint32_t ad = aAddr0 + pl * 32768 + bi * 4096 +
                                  (((2 * kk + aG) ^ sxa) << 4);
                    LDSM_X4(a[pl][bi][0], a[pl][bi][1], a[pl][bi][2], a[pl][bi][3], ad);
                }
            uint32_t b[2][4][4];                 // [plane][nquad]
            #pragma unroll
            for (int pl = 0; pl < 2; ++pl)
                #pragma unroll
                for (int i = 0; i < 4; ++i) {
                    uint32_t bd = bAddr + pl * 32768 + i * 4096 +
                                  (((2 * kk + bG) ^ sxb) << 4);
                    LDSM_X4(b[pl][i][0], b[pl][i][1], b[pl][i][2], b[pl][i][3], bd);
                }
            // 4 exact split products: A0B0 + A0B1 + A1B0 + A1B1, same accum
            #pragma unroll
            for (int ap = 0; ap < 2; ++ap)
                #pragma unroll
                for (int bp = 0; bp < 2; ++bp)
                    #pragma unroll
                    for (int bi = 0; bi < 2; ++bi)
                        #pragma unroll
                        for (int nb = 0; nb < 8; ++nb) {
                            const uint32_t* q = b[bp][nb >> 1];
                            if (nb & 1) MMA_BF16(acc[bi][nb], a[ap][bi], q[2], q[3]);
                            else        MMA_BF16(acc[bi][nb], a[ap][bi], q[0], q[1]);
                        }
        }

        // ---- fused argmin epilogue (k ascends per slot; strict '<' = first
        //      occurrence, jnp.argmin tie rule) ----
        #pragma unroll
        for (int bi = 0; bi < 2; ++bi)
            #pragma unroll
            for (int nb = 0; nb < 8; ++nb) {
                int ncol = 64 * wn + 8 * nb + 2 * (L & 3);
                float2 c2p = __ldg((const float2*)(g_c2 + k0 + ncol));
                int kidx = k0 + ncol;
                #pragma unroll
                for (int h = 0; h < 2; ++h) {
                    int r = bi * 2 + h;
                    float s0 = fmaf(-2.0f, acc[bi][nb][h * 2 + 0], c2p.x);
                    float s1 = fmaf(-2.0f, acc[bi][nb][h * 2 + 1], c2p.y);
                    if (s0 < rval[r]) { rval[r] = s0; ridx[r] = kidx; }
                    if (s1 < rval[r]) { rval[r] = s1; ridx[r] = kidx + 1; }
                }
            }
    }

    // ---- intra-CTA merge (8 slots per row), then global atomicMin ----
    __syncthreads();
    float* rv = (float*)smem;                 // reuse A region
    int*   ri = (int*)(smem + 128 * 8 * 4);
    #pragma unroll
    for (int bi = 0; bi < 2; ++bi)
        #pragma unroll
        for (int h = 0; h < 2; ++h) {
            int row  = 32 * wm + 16 * bi + 8 * h + (L >> 2);
            int slot = wn * 4 + (L & 3);
            rv[row * 8 + slot] = rval[bi * 2 + h];
            ri[row * 8 + slot] = ridx[bi * 2 + h];
        }
    __syncthreads();
    if (tid < BN) {
        float bv = rv[tid * 8];
        int   bi = ri[tid * 8];
        #pragma unroll
        for (int c = 1; c < 8; ++c) {
            float v  = rv[tid * 8 + c];
            int   id = ri[tid * 8 + c];
            if (v < bv || (v == bv && id < bi)) { bv = v; bi = id; }
        }
        unsigned long long key =
            ((unsigned long long)fkey(bv) << 32) | (unsigned int)bi;
        atomicMin(&g_best[n0 + tid], key);
    }
}

// ---------------------------------------------------------------------------
extern "C" void kernel_launch(void* const* d_in, const int* in_sizes, int n_in,
                              void* d_out, int out_size) {
    const float* latent;
    const float* coords;
    if (in_sizes[0] == NPTS * DIM) {
        latent = (const float*)d_in[0];
        coords = (const float*)d_in[1];
    } else {
        latent = (const float*)d_in[1];
        coords = (const float*)d_in[0];
    }
    float* out = (float*)d_out;

    const int smem_bytes = 196608;   // A 64K + B 2x64K
    cudaFuncSetAttribute(nn_hmma_kernel,
                         cudaFuncAttributeMaxDynamicSharedMemorySize, smem_bytes);

    init_best_kernel<<<NPTS / 256, 256>>>();
    split_lat_kernel<<<(NPTS * DIM) / 256, 256>>>(latent);
    split_coo_kernel<<<(KC * DIM) / 256, 256>>>(coords);
    c2_kernel<<<KC / 8, 256>>>(coords);
    nn_hmma_kernel<<<(NPTS / BN) * 2, 256, smem_bytes>>>();
    final_kernel<<<NPTS / 256, 256>>>(out);
}